// round 14
// baseline (speedup 1.0000x reference)
#include <cuda_runtime.h>

// WaveletSparsityLoss: 3-level Haar DWT sparsity loss on [32,1,1024,1024] fp32.
// Paired-thread streaming (R12: dense 16B-strided warp loads). Grid reduction:
// 4095 blocks publish via fire-and-forget RED.ADD (zero exit-path wait, the
// R12 property), and ONE designated poller block (launched last) spin-waits on
// a release-counter, publishes g_acc + own partial to d_out[0], and resets
// state. Removes the ~2.9us memset node AND the ~2.8us per-block ticket wait.

#define IMG          1024
#define TILES_X      128                    // 1024/8
#define TILES_PER_IMG (TILES_X * TILES_X)   // 16384
#define BATCH        32
#define TOTAL_TILES  (BATCH * TILES_PER_IMG)// 524288
#define TPB          256
#define NBLOCKS      (2 * TOTAL_TILES / TPB) // 4096 (2 threads per tile)

__device__ float        g_acc   = 0.0f;     // reset by poller each launch
__device__ unsigned int g_count = 0;        // reset by poller each launch

// Thresholds (NORMALIZE=True): thr_s = (50 / 2^(level_idx-1)) / 255
// Per-coefficient scale: weight_s / (3 * N_s)
#define THR1 (50.0f / (4.0f * 255.0f))
#define THR2 (50.0f / (2.0f * 255.0f))
#define THR3 (50.0f / 255.0f)
#define C1   (1.0f / (3.0f * 3.0f * 8388608.0f))
#define C2   (1.0f / (2.0f * 3.0f * 2097152.0f))
#define C3   (1.0f / (1.0f * 3.0f * 524288.0f))

__device__ __forceinline__ float band3(float a, float b, float c, float d, float thr,
                                       float* cA) {
    float s0 = a + b, s1 = c + d;
    float d0 = a - b, d1 = c - d;
    float cH = (s0 - s1) * 0.5f;
    float cV = (d0 + d1) * 0.5f;
    float cD = (d0 - d1) * 0.5f;
    *cA = (s0 + s1) * 0.5f;
    return fminf(fabsf(cH), thr) + fminf(fabsf(cV), thr) + fminf(fabsf(cD), thr);
}

__global__ void __launch_bounds__(TPB)
wavelet_tiles_kernel(const float* __restrict__ pred, float* __restrict__ out) {
    const int gtid = blockIdx.x * TPB + threadIdx.x;
    const int tile = gtid >> 1;               // tile id (2 threads per tile)
    const int half = gtid & 1;                // 0 = cols 0-3, 1 = cols 4-7

    const int b  = tile / TILES_PER_IMG;
    const int t  = tile - b * TILES_PER_IMG;
    const int ty = t / TILES_X;
    const int tx = t - ty * TILES_X;

    const float* base = pred + (size_t)b * (IMG * IMG)
                             + (size_t)ty * 8 * IMG + (size_t)tx * 8 + half * 4;

    // 8 rows x 4 cols: one dense float4 per row. Warp-wide: lane addresses
    // are 16B-strided -> each LDG.128 covers a contiguous 512B span.
    float x[8][4];
    #pragma unroll
    for (int row = 0; row < 8; ++row) {
        const float4 v = __ldg((const float4*)(base + (size_t)row * IMG));
        x[row][0] = v.x; x[row][1] = v.y; x[row][2] = v.z; x[row][3] = v.w;
    }

    // Level 1: 8x4 half-tile -> 4x2 cA block (8 of the tile's 16 quads).
    float A1[4][2];
    float s1 = 0.0f;
    #pragma unroll
    for (int i = 0; i < 4; ++i) {
        #pragma unroll
        for (int j = 0; j < 2; ++j) {
            s1 += band3(x[2*i][2*j], x[2*i][2*j+1], x[2*i+1][2*j], x[2*i+1][2*j+1],
                        THR1, &A1[i][j]);
        }
    }

    // Level 2: thread-local quad (this thread's A1 columns are the tile's
    // global columns {2*half, 2*half+1}).
    float A2loc[2];   // = global A2[i2][half]
    float s2 = 0.0f;
    #pragma unroll
    for (int i = 0; i < 2; ++i) {
        s2 += band3(A1[2*i][0], A1[2*i][1], A1[2*i+1][0], A1[2*i+1][1],
                    THR2, &A2loc[i]);
    }

    // Level 3: exchange the pair's A2 column via shfl. band3's loss terms are
    // invariant under (a<->b, c<->d) swap, so both threads compute the same
    // s3 and each contributes half.
    const float p0 = __shfl_xor_sync(0xffffffffu, A2loc[0], 1);
    const float p1 = __shfl_xor_sync(0xffffffffu, A2loc[1], 1);
    float cA3;
    const float s3 = band3(A2loc[0], p0, A2loc[1], p1, THR3, &cA3);

    float val = s1 * C1 + s2 * C2 + s3 * (0.5f * C3);

    // Warp tree reduce (fixed order, deterministic within block).
    #pragma unroll
    for (int off = 16; off > 0; off >>= 1)
        val += __shfl_xor_sync(0xffffffffu, val, off);

    __shared__ float warp_sums[TPB / 32];
    const int lane = threadIdx.x & 31;
    const int wid  = threadIdx.x >> 5;
    if (lane == 0) warp_sums[wid] = val;
    __syncthreads();          // the only block-wide barrier

    // Warps 1..7 retire here.
    if (threadIdx.x == 0) {
        float s = 0.0f;
        #pragma unroll
        for (int w = 0; w < TPB / 32; ++w) s += warp_sums[w];

        if (blockIdx.x != NBLOCKS - 1) {
            // Fire-and-forget: RED the partial, then a release-RED on the
            // counter (orders the partial before the count). No waits.
            atomicAdd(&g_acc, s);
            asm volatile("red.release.gpu.global.add.u32 [%0], %1;"
                         :: "l"(&g_count), "r"(1u) : "memory");
        } else {
            // Designated poller (launched last -> final wave). Wait for all
            // other blocks' releases, then publish and reset.
            unsigned int c;
            for (;;) {
                asm volatile("ld.acquire.gpu.global.u32 %0, [%1];"
                             : "=r"(c) : "l"(&g_count) : "memory");
                if (c >= NBLOCKS - 1) break;
                __nanosleep(64);
            }
            float acc;
            asm volatile("ld.acquire.gpu.global.f32 %0, [%1];"
                         : "=f"(acc) : "l"(&g_acc) : "memory");
            out[0] = acc + s;     // own partial never hit memory
            // Reset for the next graph replay (kernel completion boundary
            // publishes these before any subsequent launch).
            g_acc   = 0.0f;
            g_count = 0;
        }
    }
}

extern "C" void kernel_launch(void* const* d_in, const int* in_sizes, int n_in,
                              void* d_out, int out_size) {
    const float* pred = (const float*)d_in[0];
    float* out = (float*)d_out;
    wavelet_tiles_kernel<<<NBLOCKS, TPB>>>(pred, out);
}

// round 15
// speedup vs baseline: 1.0143x; 1.0143x over previous
#include <cuda_runtime.h>

// WaveletSparsityLoss: 3-level Haar DWT sparsity loss on [32,1,1024,1024] fp32.
// Paired-thread streaming (R12: dense 16B-strided warp loads, best measured
// streaming phase 23.3us). Grid reduction with ZERO exit-path waits:
//   - worker blocks (1..4096): fire-and-forget RED.ADD partial -> g_acc, then
//     red.release count -> g_count. No returns, no waits, no memset needed.
//   - block 0: dedicated work-free poller, starts at t=0, spins (relaxed +
//     nanosleep) until all workers counted, publishes to d_out[0] (plain
//     store, replay-safe) and resets state for the next graph replay.
// R14's poller was scheduled LAST and serialized its own tile work into the
// tail; a work-free first-scheduled poller removes that.

#define IMG          1024
#define TILES_X      128                    // 1024/8
#define TILES_PER_IMG (TILES_X * TILES_X)   // 16384
#define BATCH        32
#define TOTAL_TILES  (BATCH * TILES_PER_IMG)// 524288
#define TPB          256
#define NWORKERS     (2 * TOTAL_TILES / TPB) // 4096 worker blocks
#define NBLOCKS      (NWORKERS + 1)          // + 1 poller block (block 0)

// Separate cache lines to keep the counter polling off the accumulator line.
__device__ __align__(128) float        g_acc   = 0.0f;  // reset by poller
__device__ __align__(128) unsigned int g_count = 0;     // reset by poller

// Thresholds (NORMALIZE=True): thr_s = (50 / 2^(level_idx-1)) / 255
// Per-coefficient scale: weight_s / (3 * N_s)
#define THR1 (50.0f / (4.0f * 255.0f))
#define THR2 (50.0f / (2.0f * 255.0f))
#define THR3 (50.0f / 255.0f)
#define C1   (1.0f / (3.0f * 3.0f * 8388608.0f))
#define C2   (1.0f / (2.0f * 3.0f * 2097152.0f))
#define C3   (1.0f / (1.0f * 3.0f * 524288.0f))

__device__ __forceinline__ float band3(float a, float b, float c, float d, float thr,
                                       float* cA) {
    float s0 = a + b, s1 = c + d;
    float d0 = a - b, d1 = c - d;
    float cH = (s0 - s1) * 0.5f;
    float cV = (d0 + d1) * 0.5f;
    float cD = (d0 - d1) * 0.5f;
    *cA = (s0 + s1) * 0.5f;
    return fminf(fabsf(cH), thr) + fminf(fabsf(cV), thr) + fminf(fabsf(cD), thr);
}

__global__ void __launch_bounds__(TPB)
wavelet_tiles_kernel(const float* __restrict__ pred, float* __restrict__ out) {
    // ---- Block 0: dedicated work-free poller (scheduled first). ----
    if (blockIdx.x == 0) {
        if (threadIdx.x == 0) {
            unsigned int c;
            for (;;) {
                // Relaxed poll (cheap); backoff keeps L2 line traffic low.
                asm volatile("ld.relaxed.gpu.global.u32 %0, [%1];"
                             : "=r"(c) : "l"(&g_count) : "memory");
                if (c >= NWORKERS) break;
                __nanosleep(128);
            }
            // Acquire: sync-with the workers' release-REDs -> all g_acc
            // contributions are visible.
            asm volatile("ld.acquire.gpu.global.u32 %0, [%1];"
                         : "=r"(c) : "l"(&g_count) : "memory");
            float acc;
            asm volatile("ld.relaxed.gpu.global.f32 %0, [%1];"
                         : "=f"(acc) : "l"(&g_acc) : "memory");
            out[0] = acc;             // plain store: replay-safe
            // Reset for the next graph replay (kernel completion boundary
            // publishes these before any subsequent launch's accesses).
            g_acc   = 0.0f;
            g_count = 0;
        }
        return;   // warps 1..7 of block 0 retire immediately
    }

    // ---- Worker blocks: R12 streaming, fire-and-forget exit. ----
    const int gtid = (blockIdx.x - 1) * TPB + threadIdx.x;
    const int tile = gtid >> 1;               // tile id (2 threads per tile)
    const int half = gtid & 1;                // 0 = cols 0-3, 1 = cols 4-7

    const int b  = tile / TILES_PER_IMG;
    const int t  = tile - b * TILES_PER_IMG;
    const int ty = t / TILES_X;
    const int tx = t - ty * TILES_X;

    const float* base = pred + (size_t)b * (IMG * IMG)
                             + (size_t)ty * 8 * IMG + (size_t)tx * 8 + half * 4;

    // 8 rows x 4 cols: one dense float4 per row. Warp-wide: lane addresses
    // are 16B-strided -> each LDG.128 covers a contiguous 512B span.
    float x[8][4];
    #pragma unroll
    for (int row = 0; row < 8; ++row) {
        const float4 v = __ldg((const float4*)(base + (size_t)row * IMG));
        x[row][0] = v.x; x[row][1] = v.y; x[row][2] = v.z; x[row][3] = v.w;
    }

    // Level 1: 8x4 half-tile -> 4x2 cA block (8 of the tile's 16 quads).
    float A1[4][2];
    float s1 = 0.0f;
    #pragma unroll
    for (int i = 0; i < 4; ++i) {
        #pragma unroll
        for (int j = 0; j < 2; ++j) {
            s1 += band3(x[2*i][2*j], x[2*i][2*j+1], x[2*i+1][2*j], x[2*i+1][2*j+1],
                        THR1, &A1[i][j]);
        }
    }

    // Level 2: thread-local quad (this thread's A1 columns are the tile's
    // global columns {2*half, 2*half+1}).
    float A2loc[2];   // = global A2[i2][half]
    float s2 = 0.0f;
    #pragma unroll
    for (int i = 0; i < 2; ++i) {
        s2 += band3(A1[2*i][0], A1[2*i][1], A1[2*i+1][0], A1[2*i+1][1],
                    THR2, &A2loc[i]);
    }

    // Level 3: exchange the pair's A2 column via shfl. band3's loss terms are
    // invariant under (a<->b, c<->d) swap, so both threads compute the same
    // s3 and each contributes half.
    const float p0 = __shfl_xor_sync(0xffffffffu, A2loc[0], 1);
    const float p1 = __shfl_xor_sync(0xffffffffu, A2loc[1], 1);
    float cA3;
    const float s3 = band3(A2loc[0], p0, A2loc[1], p1, THR3, &cA3);

    float val = s1 * C1 + s2 * C2 + s3 * (0.5f * C3);

    // Warp tree reduce (fixed order, deterministic within block).
    #pragma unroll
    for (int off = 16; off > 0; off >>= 1)
        val += __shfl_xor_sync(0xffffffffu, val, off);

    __shared__ float warp_sums[TPB / 32];
    const int lane = threadIdx.x & 31;
    const int wid  = threadIdx.x >> 5;
    if (lane == 0) warp_sums[wid] = val;
    __syncthreads();          // the only block-wide barrier

    // Warps 1..7 retire here. Thread 0: two fire-and-forget REDs, no waits.
    if (threadIdx.x == 0) {
        float s = 0.0f;
        #pragma unroll
        for (int w = 0; w < TPB / 32; ++w) s += warp_sums[w];

        atomicAdd(&g_acc, s);   // result unused -> RED.ADD.F32, no wait
        // Release: orders the RED above before the count increment.
        asm volatile("red.release.gpu.global.add.u32 [%0], %1;"
                     :: "l"(&g_count), "r"(1u) : "memory");
    }
}

extern "C" void kernel_launch(void* const* d_in, const int* in_sizes, int n_in,
                              void* d_out, int out_size) {
    const float* pred = (const float*)d_in[0];
    float* out = (float*)d_out;
    wavelet_tiles_kernel<<<NBLOCKS, TPB>>>(pred, out);
}

// round 16
// speedup vs baseline: 1.0759x; 1.0607x over previous
#include <cuda_runtime.h>

// WaveletSparsityLoss: 3-level Haar DWT sparsity loss on [32,1,1024,1024] fp32.
// Paired-thread streaming (R12: dense 16B-strided warp loads). Grid reduction
// via a SINGLE 64-bit fixed-point RED per worker block:
//   packed = (1<<48) + round(partial * 2^45)
// Count (bits>=48) and sum (bits<48) travel in one atomic word, so the poller
// (work-free block 0) needs no acquire/release at all: when count==NWORKERS,
// the sum in the same word is complete. Integer adds are exactly associative
// -> deterministic. All loss terms are >=0 -> no sign issues; max sum ~2^42.

#define IMG          1024
#define TILES_X      128                    // 1024/8
#define TILES_PER_IMG (TILES_X * TILES_X)   // 16384
#define BATCH        32
#define TOTAL_TILES  (BATCH * TILES_PER_IMG)// 524288
#define TPB          256
#define NWORKERS     (2 * TOTAL_TILES / TPB) // 4096 worker blocks
#define NBLOCKS      (NWORKERS + 1)          // + 1 poller block (block 0)

#define FIXED_SCALE  35184372088832.0        // 2^45
#define COUNT_ONE    (1ULL << 48)
#define SUM_MASK     (COUNT_ONE - 1ULL)

__device__ __align__(128) unsigned long long g_pack = 0ULL;  // reset by poller

// Thresholds (NORMALIZE=True): thr_s = (50 / 2^(level_idx-1)) / 255
// Per-coefficient scale: weight_s / (3 * N_s)
#define THR1 (50.0f / (4.0f * 255.0f))
#define THR2 (50.0f / (2.0f * 255.0f))
#define THR3 (50.0f / 255.0f)
#define C1   (1.0f / (3.0f * 3.0f * 8388608.0f))
#define C2   (1.0f / (2.0f * 3.0f * 2097152.0f))
#define C3   (1.0f / (1.0f * 3.0f * 524288.0f))

__device__ __forceinline__ float band3(float a, float b, float c, float d, float thr,
                                       float* cA) {
    float s0 = a + b, s1 = c + d;
    float d0 = a - b, d1 = c - d;
    float cH = (s0 - s1) * 0.5f;
    float cV = (d0 + d1) * 0.5f;
    float cD = (d0 - d1) * 0.5f;
    *cA = (s0 + s1) * 0.5f;
    return fminf(fabsf(cH), thr) + fminf(fabsf(cV), thr) + fminf(fabsf(cD), thr);
}

__global__ void __launch_bounds__(TPB)
wavelet_tiles_kernel(const float* __restrict__ pred, float* __restrict__ out) {
    // ---- Block 0: dedicated work-free poller (scheduled first). ----
    if (blockIdx.x == 0) {
        if (threadIdx.x == 0) {
            unsigned long long v;
            for (;;) {
                asm volatile("ld.relaxed.gpu.global.u64 %0, [%1];"
                             : "=l"(v) : "l"(&g_pack) : "memory");
                if ((v >> 48) >= (unsigned long long)NWORKERS) break;
                __nanosleep(64);
            }
            // Count complete => sum bits in the same word are complete.
            out[0] = (float)((double)(v & SUM_MASK) * (1.0 / FIXED_SCALE));
            g_pack = 0ULL;   // reset for next graph replay
        }
        return;   // warps 1..7 of block 0 retire immediately
    }

    // ---- Worker blocks: R12 streaming, single fire-and-forget RED exit. ----
    const int gtid = (blockIdx.x - 1) * TPB + threadIdx.x;
    const int tile = gtid >> 1;               // tile id (2 threads per tile)
    const int half = gtid & 1;                // 0 = cols 0-3, 1 = cols 4-7

    const int b  = tile / TILES_PER_IMG;
    const int t  = tile - b * TILES_PER_IMG;
    const int ty = t / TILES_X;
    const int tx = t - ty * TILES_X;

    const float* base = pred + (size_t)b * (IMG * IMG)
                             + (size_t)ty * 8 * IMG + (size_t)tx * 8 + half * 4;

    // 8 rows x 4 cols: one dense float4 per row. Warp-wide: lane addresses
    // are 16B-strided -> each LDG.128 covers a contiguous 512B span.
    float x[8][4];
    #pragma unroll
    for (int row = 0; row < 8; ++row) {
        const float4 v = __ldg((const float4*)(base + (size_t)row * IMG));
        x[row][0] = v.x; x[row][1] = v.y; x[row][2] = v.z; x[row][3] = v.w;
    }

    // Level 1: 8x4 half-tile -> 4x2 cA block (8 of the tile's 16 quads).
    float A1[4][2];
    float s1 = 0.0f;
    #pragma unroll
    for (int i = 0; i < 4; ++i) {
        #pragma unroll
        for (int j = 0; j < 2; ++j) {
            s1 += band3(x[2*i][2*j], x[2*i][2*j+1], x[2*i+1][2*j], x[2*i+1][2*j+1],
                        THR1, &A1[i][j]);
        }
    }

    // Level 2: thread-local quad (this thread's A1 columns are the tile's
    // global columns {2*half, 2*half+1}).
    float A2loc[2];   // = global A2[i2][half]
    float s2 = 0.0f;
    #pragma unroll
    for (int i = 0; i < 2; ++i) {
        s2 += band3(A1[2*i][0], A1[2*i][1], A1[2*i+1][0], A1[2*i+1][1],
                    THR2, &A2loc[i]);
    }

    // Level 3: exchange the pair's A2 column via shfl. band3's loss terms are
    // invariant under (a<->b, c<->d) swap, so both threads compute the same
    // s3 and each contributes half.
    const float p0 = __shfl_xor_sync(0xffffffffu, A2loc[0], 1);
    const float p1 = __shfl_xor_sync(0xffffffffu, A2loc[1], 1);
    float cA3;
    const float s3 = band3(A2loc[0], p0, A2loc[1], p1, THR3, &cA3);

    float val = s1 * C1 + s2 * C2 + s3 * (0.5f * C3);

    // Warp tree reduce (fixed order, deterministic within block).
    #pragma unroll
    for (int off = 16; off > 0; off >>= 1)
        val += __shfl_xor_sync(0xffffffffu, val, off);

    __shared__ float warp_sums[TPB / 32];
    const int lane = threadIdx.x & 31;
    const int wid  = threadIdx.x >> 5;
    if (lane == 0) warp_sums[wid] = val;
    __syncthreads();          // the only block-wide barrier

    // Warps 1..7 retire here. Thread 0: ONE fire-and-forget 64-bit RED.
    if (threadIdx.x == 0) {
        float s = 0.0f;
        #pragma unroll
        for (int w = 0; w < TPB / 32; ++w) s += warp_sums[w];

        // Pack count (bits >=48) + fixed-point partial (bits <48). Partials
        // are non-negative; max packed sum ~2^42, no overflow into count.
        const unsigned long long packed =
            COUNT_ONE + (unsigned long long)((double)s * FIXED_SCALE);
        asm volatile("red.relaxed.gpu.global.add.u64 [%0], %1;"
                     :: "l"(&g_pack), "l"(packed) : "memory");
    }
}

extern "C" void kernel_launch(void* const* d_in, const int* in_sizes, int n_in,
                              void* d_out, int out_size) {
    const float* pred = (const float*)d_in[0];
    float* out = (float*)d_out;
    wavelet_tiles_kernel<<<NBLOCKS, TPB>>>(pred, out);
}